// round 16
// baseline (speedup 1.0000x reference)
#include <cuda_runtime.h>
#include <cuda_fp16.h>
#include <math.h>
#include <stdint.h>

#define B_  8
#define L_  2048
#define D_  512
#define BL_ (B_*L_)          // 16384
#define POOLED_ELEMS ((size_t)BL_ * D_)   // 8388608
#define LDP 1024             // packed [V | Hn] row stride (halves)

// ---------------- scratch ----------------
__device__ float g_nrm[BL_];
__device__ float g_G[BL_ * D_];
__device__ __half g_Ph[(size_t)BL_ * LDP];   // fp16 packed [V | Hn]
__device__ __half g_Nhi[BL_ * D_];  // normh split — general (non-eye) path only
__device__ __half g_Nlo[BL_ * D_];
__device__ __half g_Ahi[BL_ * D_];  // hidden (fp16)
__device__ __half g_Whi[2 * D_ * D_];   // stacked [Wv ; NT]  (fp16)
__device__ __half g_WkThi[D_ * D_];
__device__ __half g_WkTlo[D_ * D_];
__device__ __half g_WqThi[D_ * D_];
__device__ __half g_WqTlo[D_ * D_];
__device__ __half g_QbThi[D_ * D_];
__device__ __half g_QbTlo[D_ * D_];
__device__ __half g_KbThi[D_ * D_];
__device__ __half g_KbTlo[D_ * D_];
__device__ __half g_Mhi[D_ * D_];
__device__ __half g_Mlo[D_ * D_];
__device__ int   g_hard[BL_];
__device__ int   g_segstart[BL_];
__device__ int   g_segcount[BL_];
__device__ int   g_nseg[B_];
__device__ int   g_isIw = 1;        // 1 if Wqb == Wkb == identity; reset at end of run

// ---------------- helpers ----------------
__device__ __forceinline__ uint32_t smem_u32(const void* p) {
    uint32_t a;
    asm("{ .reg .u64 t; cvta.to.shared.u64 t, %1; cvt.u32.u64 %0, t; }" : "=r"(a) : "l"(p));
    return a;
}
__device__ __forceinline__ float warpReduceSum(float v) {
    #pragma unroll
    for (int o = 16; o; o >>= 1) v += __shfl_xor_sync(0xffffffffu, v, o);
    return v;
}
__device__ __forceinline__ void split_f16(float x, __half& h, __half& l) {
    h = __float2half_rn(x);
    l = __float2half_rn(x - __half2float(h));
}
__device__ __forceinline__ float4 ld4h(const __half* p) {
    uint2 u = *(const uint2*)p;
    __half2 h0 = *(__half2*)&u.x;
    __half2 h1 = *(__half2*)&u.y;
    float2 f0 = __half22float2(h0);
    float2 f1 = __half22float2(h1);
    return make_float4(f0.x, f0.y, f1.x, f1.y);
}

#define LDM4(r, addr) \
    asm volatile("ldmatrix.sync.aligned.m8n8.x4.shared.b16 {%0,%1,%2,%3}, [%4];" \
        : "=r"((r)[0]), "=r"((r)[1]), "=r"((r)[2]), "=r"((r)[3]) : "r"(addr))

#define MMA_F16(d, a, b) \
    asm volatile("mma.sync.aligned.m16n8k16.row.col.f32.f16.f16.f32 " \
        "{%0,%1,%2,%3}, {%4,%5,%6,%7}, {%8,%9}, {%0,%1,%2,%3};" \
        : "+f"((d)[0]), "+f"((d)[1]), "+f"((d)[2]), "+f"((d)[3]) \
        : "r"((a)[0]), "r"((a)[1]), "r"((a)[2]), "r"((a)[3]), "r"((b)[0]), "r"((b)[1]))

#define CP16(dst, src) \
    asm volatile("cp.async.cg.shared.global [%0], [%1], 16;" :: "r"(dst), "l"(src))
#define CP_COMMIT() asm volatile("cp.async.commit_group;" ::: "memory")
#define CP_WAIT2()  asm volatile("cp.async.wait_group 2;" ::: "memory")
#define CP_WAIT1()  asm volatile("cp.async.wait_group 1;" ::: "memory")
#define CP_WAIT0()  asm volatile("cp.async.wait_group 0;" ::: "memory")

// ---------------- fused prep: identity check + Wv cvt + 4 transposes ----------------
__global__ __launch_bounds__(256) void prep_kernel(const float* __restrict__ wqb,
                                                   const float* __restrict__ wkb,
                                                   const float* __restrict__ wq,
                                                   const float* __restrict__ wk,
                                                   const float* __restrict__ wv) {
    int bx = blockIdx.x;
    if (bx < 512) {
        const float* src = (bx < 256) ? wqb : wkb;
        size_t i = (size_t)(bx & 255) * 256 + threadIdx.x;
        float4 v = ((const float4*)src)[i];
        size_t e0 = 4 * i;
        int row = (int)(e0 >> 9);
        int col = (int)(e0 & 511);
        bool ok = (v.x == ((col + 0 == row) ? 1.0f : 0.0f)) &
                  (v.y == ((col + 1 == row) ? 1.0f : 0.0f)) &
                  (v.z == ((col + 2 == row) ? 1.0f : 0.0f)) &
                  (v.w == ((col + 3 == row) ? 1.0f : 0.0f));
        if (!__syncthreads_and(ok)) {
            if (threadIdx.x == 0) atomicExch(&g_isIw, 0);
        }
    } else if (bx < 768) {
        size_t local = (size_t)(bx - 512) * 256 + threadIdx.x;
        float4 v = ((const float4*)wv)[local];
        __half hh[4];
        hh[0] = __float2half_rn(v.x); hh[1] = __float2half_rn(v.y);
        hh[2] = __float2half_rn(v.z); hh[3] = __float2half_rn(v.w);
        *(uint2*)(g_Whi + 4 * local) = *(uint2*)hh;
    } else {
        int t = bx - 768;
        int which = t >> 8;                 // 0:Wq 1:Wk 2:Wqb 3:Wkb
        int tb = t & 255;
        const float* in = (which == 0) ? wq : (which == 1) ? wk : (which == 2) ? wqb : wkb;
        __half* ohi = (which == 0) ? g_WqThi : (which == 1) ? g_WkThi : (which == 2) ? g_QbThi : g_KbThi;
        __half* olo = (which == 0) ? g_WqTlo : (which == 1) ? g_WkTlo : (which == 2) ? g_QbTlo : g_KbTlo;
        int bxx = tb & 15, byy = tb >> 4;
        int tx = threadIdx.x & 31, ty = threadIdx.x >> 5;
        __shared__ float tile[32][33];
        int x = bxx * 32 + tx;
        int y = byy * 32 + ty;
        #pragma unroll
        for (int i = 0; i < 32; i += 8)
            tile[ty + i][tx] = in[(size_t)(y + i) * 512 + x];
        __syncthreads();
        x = byy * 32 + tx;
        y = bxx * 32 + ty;
        #pragma unroll
        for (int i = 0; i < 32; i += 8) {
            float v = tile[tx][ty + i];
            __half h, l;
            split_f16(v, h, l);
            ohi[(size_t)(y + i) * 512 + x] = h;
            olo[(size_t)(y + i) * 512 + x] = l;
        }
    }
}

// ---------------- rownorm: norms + fp16 hidden (+ normh splits on general path) ----------------
__global__ __launch_bounds__(128) void rownorm_split_kernel(const float* __restrict__ h) {
    int row = blockIdx.x;
    const float4* hr = (const float4*)(h + (size_t)row * D_);
    float4 v = hr[threadIdx.x];
    float ss = v.x*v.x + v.y*v.y + v.z*v.z + v.w*v.w;
    __shared__ float sm[4];
    int lane = threadIdx.x & 31, w = threadIdx.x >> 5;
    ss = warpReduceSum(ss);
    if (lane == 0) sm[w] = ss;
    __syncthreads();
    float tot = sm[0] + sm[1] + sm[2] + sm[3];
    float nrm = fmaxf(sqrtf(tot), 1e-12f);
    if (threadIdx.x == 0) g_nrm[row] = nrm;
    size_t base = (size_t)row * D_ + threadIdx.x * 4;
    __half hh[4], ll[4];
    hh[0] = __float2half_rn(v.x); hh[1] = __float2half_rn(v.y);
    hh[2] = __float2half_rn(v.z); hh[3] = __float2half_rn(v.w);
    *(uint2*)(g_Ahi + base) = *(uint2*)hh;
    if (!g_isIw) {
        float4 o;
        o.x = v.x / nrm; o.y = v.y / nrm; o.z = v.z / nrm; o.w = v.w / nrm;
        split_f16(o.x, hh[0], ll[0]); split_f16(o.y, hh[1], ll[1]);
        split_f16(o.z, hh[2], ll[2]); split_f16(o.w, hh[3], ll[3]);
        *(uint2*)(g_Nhi + base) = *(uint2*)hh;
        *(uint2*)(g_Nlo + base) = *(uint2*)ll;
    }
}

// ---------------- pipelined split-fp16 HMMA GEMM body ----------------
// OMODE: 0 = fp32 out, 1 = fp16 out, 2 = fp16 hi/lo split out (Cv, Cv2)
#define APITCH 40
#define GARR   (128 * APITCH * 2)   // 10240 B per array
#define GSTAGE (4 * GARR)           // 40960 B per 3-pass stage
#define GSMEM  (2 * GSTAGE)         // 81920 B

template<int NPASS, int OMODE>
__device__ __forceinline__ void gemm_body(
    const __half* __restrict__ Ahi, const __half* __restrict__ Alo,
    const __half* __restrict__ Bhi, const __half* __restrict__ Blo,
    void* __restrict__ Cv, void* __restrict__ Cv2, int ldc, int m0, int n0, char* smem)
{
    int tid = threadIdx.x;
    int lane = tid & 31, wid = tid >> 5;
    int warp_m = wid >> 1;
    int warp_n = wid & 1;

    float acc[2][8][4];
    #pragma unroll
    for (int mt = 0; mt < 2; mt++)
        #pragma unroll
        for (int nt = 0; nt < 8; nt++)
            #pragma unroll
            for (int r = 0; r < 4; r++) acc[mt][nt][r] = 0.f;

    uint32_t sbase = smem_u32(smem);
    int lrow  = tid >> 1;
    int lslot = (tid & 1) * 2;

    int a_r  = lane & 15;
    int a_c8 = (lane >> 4) * 8;
    int b_r  = (lane & 7) + ((lane >> 4) * 8);
    int b_c8 = ((lane >> 3) & 1) * 8;

    auto compute = [&](uint32_t aB, uint32_t alB, uint32_t bB, uint32_t blB) {
        #pragma unroll
        for (int ks = 0; ks < 2; ks++) {
            int kofs = ks * 16;
            uint32_t ahi[2][4], alo[2][4];
            #pragma unroll
            for (int mt = 0; mt < 2; mt++) {
                int r = warp_m * 32 + mt * 16 + a_r;
                uint32_t ab = (uint32_t)(r * APITCH + kofs + a_c8) * 2;
                LDM4(ahi[mt], aB + ab);
                if (NPASS >= 2) LDM4(alo[mt], alB + ab);
            }
            #pragma unroll
            for (int nt2 = 0; nt2 < 4; nt2++) {
                int r = warp_n * 64 + nt2 * 16 + b_r;
                uint32_t bb = (uint32_t)(r * APITCH + kofs + b_c8) * 2;
                uint32_t bhi[4], blo[4];
                LDM4(bhi, bB + bb);
                if (NPASS == 3) LDM4(blo, blB + bb);
                #pragma unroll
                for (int half = 0; half < 2; half++) {
                    int nt = nt2 * 2 + half;
                    uint32_t* bh = bhi + half * 2;
                    uint32_t* bl = blo + half * 2;
                    #pragma unroll
                    for (int mt = 0; mt < 2; mt++) {
                        MMA_F16(acc[mt][nt], ahi[mt], bh);
                        if (NPASS >= 2) MMA_F16(acc[mt][nt], alo[mt], bh);
                        if (NPASS == 3) MMA_F16(acc[mt][nt], ahi[mt], bl);
                    }
                }
            }
        }
    };

    if (NPASS == 1) {
        const uint32_t STG = 2 * GARR;
        auto load1 = [&](int kc, uint32_t st) {
            int gk = kc * 32;
            #pragma unroll
            for (int s = 0; s < 2; s++) {
                int slot = lslot + s;
                size_t goff = (size_t)(m0 + lrow) * 512 + gk + slot * 8;
                size_t boff = (size_t)(n0 + lrow) * 512 + gk + slot * 8;
                uint32_t soff = (uint32_t)(lrow * APITCH + slot * 8) * 2;
                CP16(st + soff,        Ahi + goff);
                CP16(st + GARR + soff, Bhi + boff);
            }
            CP_COMMIT();
        };
        load1(0, sbase + 0 * STG);
        load1(1, sbase + 1 * STG);
        for (int kc = 0; kc < 16; kc++) {
            if (kc + 2 < 16) {
                load1(kc + 2, sbase + (uint32_t)((kc + 2) & 3) * STG);
                CP_WAIT2();
            } else {
                CP_WAIT0();
            }
            __syncthreads();
            uint32_t cur = sbase + (uint32_t)(kc & 3) * STG;
            compute(cur, cur, cur + GARR, cur + GARR);
        }
    } else {
        auto load3 = [&](int kc, uint32_t st) {
            int gk = kc * 32;
            #pragma unroll
            for (int s = 0; s < 2; s++) {
                int slot = lslot + s;
                size_t goff = (size_t)(m0 + lrow) * 512 + gk + slot * 8;
                size_t boff = (size_t)(n0 + lrow) * 512 + gk + slot * 8;
                uint32_t soff = (uint32_t)(lrow * APITCH + slot * 8) * 2;
                CP16(st + 0*GARR + soff, Ahi + goff);
                CP16(st + 1*GARR + soff, Alo + goff);
                CP16(st + 2*GARR + soff, Bhi + boff);
                CP16(st + 3*GARR + soff, Blo + boff);
            }
            CP_COMMIT();
        };
        load3(0, sbase);
        for (int kc = 0; kc < 16; kc++) {
            uint32_t cur = sbase + (uint32_t)(kc & 1) * GSTAGE;
            if (kc + 1 < 16) {
                load3(kc + 1, sbase + (uint32_t)((kc + 1) & 1) * GSTAGE);
                CP_WAIT1();
            } else {
                CP_WAIT0();
            }
            __syncthreads();
            compute(cur + 0*GARR, cur + 1*GARR, cur + 2*GARR, cur + 3*GARR);
            __syncthreads();
        }
    }

    #pragma unroll
    for (int mt = 0; mt < 2; mt++) {
        int r0 = m0 + warp_m * 32 + mt * 16 + (lane >> 2);
        #pragma unroll
        for (int nt = 0; nt < 8; nt++) {
            int c = n0 + warp_n * 64 + nt * 8 + (lane & 3) * 2;
            if (OMODE == 1) {
                __half* C = (__half*)Cv;
                *(__half2*)(C + (size_t)r0 * ldc + c) =
                    __floats2half2_rn(acc[mt][nt][0], acc[mt][nt][1]);
                *(__half2*)(C + (size_t)(r0 + 8) * ldc + c) =
                    __floats2half2_rn(acc[mt][nt][2], acc[mt][nt][3]);
            } else if (OMODE == 2) {
                __half* Ch = (__half*)Cv;
                __half* Cl = (__half*)Cv2;
                __half h0, l0, h1, l1;
                split_f16(acc[mt][nt][0], h0, l0); split_f16(acc[mt][nt][1], h1, l1);
                *(__half2*)(Ch + (size_t)r0 * ldc + c) = __half2(h0, h1);
                *(__half2*)(Cl + (size_t)r0 * ldc + c) = __half2(l0, l1);
                split_f16(acc[mt][nt][2], h0, l0); split_f16(acc[mt][nt][3], h1, l1);
                *(__half2*)(Ch + (size_t)(r0 + 8) * ldc + c) = __half2(h0, h1);
                *(__half2*)(Cl + (size_t)(r0 + 8) * ldc + c) = __half2(l0, l1);
            } else {
                float* C = (float*)Cv;
                *(float2*)(C + (size_t)r0 * ldc + c)       = make_float2(acc[mt][nt][0], acc[mt][nt][1]);
                *(float2*)(C + (size_t)(r0 + 8) * ldc + c) = make_float2(acc[mt][nt][2], acc[mt][nt][3]);
            }
        }
    }
}

// fused small GEMMs: bx<4 -> NT = Wk^T Wq (fp16 out); bx>=4 -> M split-fp16 out (gated)
__global__ __launch_bounds__(256, 2) void small_gemms() {
    extern __shared__ char smem[];
    int bx = blockIdx.x;
    int m0 = blockIdx.y * 128;
    if (bx < 4) {
        gemm_body<3, 1>(g_WkThi, g_WkTlo, g_WqThi, g_WqTlo,
                        g_Whi + (size_t)D_ * D_, nullptr, 512, m0, bx * 128, smem);
    } else {
        if (g_isIw) return;
        gemm_body<3, 2>(g_QbThi, g_QbTlo, g_KbThi, g_KbTlo,
                        g_Mhi, g_Mlo, 512, m0, (bx - 4) * 128, smem);
    }
}

// merged big GEMM: bx<8 -> P tile (1-pass, fp16 out, [V|Hn]); bx>=8 -> G tile (gated)
__global__ __launch_bounds__(256, 2) void mma_gemm_merged() {
    extern __shared__ char smem[];
    int bx = blockIdx.x;
    int m0 = blockIdx.y * 128;
    if (bx < 8) {
        gemm_body<1, 1>(g_Ahi, g_Ahi, g_Whi, g_Whi, g_Ph, nullptr, LDP, m0, bx * 128, smem);
    } else {
        if (g_isIw) return;
        gemm_body<3, 0>(g_Nhi, g_Nlo, g_Mhi, g_Mlo, g_G, nullptr, 512, m0, (bx - 8) * 128, smem);
    }
}

// ---------------- boundary decisions (reads hidden + norms; normh never stored) ----------------
__global__ __launch_bounds__(256) void boundary_kernel(const float* __restrict__ hidden,
                                                       const float* __restrict__ noise_u) {
    int gw = blockIdx.x * 8 + (threadIdx.x >> 5);
    if (gw >= BL_) return;
    int t = gw & (L_ - 1);
    int lane = threadIdx.x & 31;
    float prob;
    if (t == 0) {
        prob = 1.0f;
    } else {
        int isI = g_isIw;
        float n1 = g_nrm[gw - 1];
        float n2 = isI ? g_nrm[gw] : 1.0f;
        const float4* x = (const float4*)(hidden + (size_t)(gw - 1) * D_);
        const float4* y = isI ? (const float4*)(hidden + (size_t)gw * D_)
                              : (const float4*)(g_G + (size_t)gw * D_);
        float s = 0.0f;
        #pragma unroll
        for (int i = 0; i < 4; i++) {
            float4 aa = x[lane + i*32];
            float4 cc = y[lane + i*32];
            // identical fp32 divisions to the former rownorm path -> bit-identical cos
            float ax = aa.x / n1, ay = aa.y / n1, az = aa.z / n1, aw = aa.w / n1;
            float cx = cc.x / n2, cy = cc.y / n2, cz = cc.z / n2, cw = cc.w / n2;
            s += ax*cx + ay*cy + az*cz + aw*cw;
        }
        s = warpReduceSum(s);
        prob = (1.0f - s) * 0.5f;
        prob = fminf(fmaxf(prob, 0.0f), 1.0f);
    }
    if (lane == 0) {
        float pc = fminf(fmaxf(prob, 1e-6f), 1.0f - 1e-6f);
        float logits = logf(pc) - log1pf(-pc);
        float u = noise_u[gw];
        float noise = logf(u) - log1pf(-u);
        float z = logits + noise;
        float soft = 1.0f / (1.0f + expf(-z));
        g_hard[gw] = (soft > 0.5f) ? 1 : 0;
    }
}

// ---------------- per-batch segmentation (warp-shuffle scan) ----------------
__global__ __launch_bounds__(1024) void scan_kernel() {
    int b = blockIdx.x;
    __shared__ int wsum[32];
    __shared__ int st[L_];
    __shared__ int ns_sh;
    int tid = threadIdx.x, lane = tid & 31, warp = tid >> 5;
    int h0 = g_hard[b*L_ + 2*tid];
    int h1 = g_hard[b*L_ + 2*tid + 1];
    int v = h0 + h1;
    int x = v;
    #pragma unroll
    for (int o = 1; o < 32; o <<= 1) {
        int y = __shfl_up_sync(0xffffffffu, x, o);
        if (lane >= o) x += y;
    }
    if (lane == 31) wsum[warp] = x;
    __syncthreads();
    if (warp == 0) {
        int tsum = wsum[lane];
        #pragma unroll
        for (int o = 1; o < 32; o <<= 1) {
            int y = __shfl_up_sync(0xffffffffu, tsum, o);
            if (lane >= o) tsum += y;
        }
        wsum[lane] = tsum;
        if (lane == 31) { ns_sh = tsum; g_nseg[b] = tsum; }
    }
    __syncthreads();
    int incl = x + (warp ? wsum[warp - 1] : 0);
    int excl = incl - v;
    int i0 = excl + h0;
    int i1 = excl + h0 + h1;
    if (h0) st[i0 - 1] = 2*tid;
    if (h1) st[i1 - 1] = 2*tid + 1;
    __syncthreads();
    int ns = ns_sh;
    for (int s = tid; s < ns; s += 1024) {
        int sbgn = st[s];
        int send = (s + 1 < ns) ? st[s + 1] : L_;
        g_segstart[b*L_ + s] = sbgn;
        g_segcount[b*L_ + s] = send - sbgn;
    }
}

// ---------------- warp-per-segment attention + fused loss/scalars ----------------
__global__ __launch_bounds__(256) void attn_warp_kernel(float* __restrict__ out) {
    int b = blockIdx.y;
    int w = threadIdx.x >> 5, lane = threadIdx.x & 31;
    int s = blockIdx.x * 8 + w;
    size_t orow = (size_t)(b*L_ + s) * D_;

    if (s < g_nseg[b]) {
        int start = g_segstart[b*L_ + s];
        int cnt   = g_segcount[b*L_ + s];

        float q[16];
        #pragma unroll
        for (int i = 0; i < 16; i++) q[i] = 0.f;
        for (int l = 0; l < cnt; l++) {
            const __half* hn = g_Ph + (size_t)(b*L_ + start + l) * LDP + 512;
            #pragma unroll
            for (int i = 0; i < 4; i++) {
                float4 v = ld4h(hn + (lane + i*32) * 4);
                q[4*i+0] += v.x; q[4*i+1] += v.y; q[4*i+2] += v.z; q[4*i+3] += v.w;
            }
        }
        float invc = 1.0f / (float)cnt;
        #pragma unroll
        for (int i = 0; i < 16; i++) q[i] *= invc;

        const float scale = 0.04419417382415922f;   // 512^-0.5
        float m = -INFINITY, lsum = 0.f;
        float acc[16];
        #pragma unroll
        for (int i = 0; i < 16; i++) acc[i] = 0.f;

        for (int l = 0; l < cnt; l++) {
            const __half* hr = g_Ahi + (size_t)(b*L_ + start + l) * D_;
            float dp = 0.f;
            #pragma unroll
            for (int i = 0; i < 4; i++) {
                float4 kk = ld4h(hr + (lane + i*32) * 4);
                dp += q[4*i+0]*kk.x + q[4*i+1]*kk.y + q[4*i+2]*kk.z + q[4*i+3]*kk.w;
            }
            dp = warpReduceSum(dp) * scale;
            float mn = fmaxf(m, dp);
            float so = expf(m - mn);
            float e  = expf(dp - mn);
            lsum = lsum * so + e;
            const __half* vr = g_Ph + (size_t)(b*L_ + start + l) * LDP;
            #pragma unroll
            for (int i = 0; i < 4; i++) {
                float4 vv = ld4h(vr + (lane + i*32) * 4);
                acc[4*i+0] = acc[4*i+0]*so + e*vv.x;
                acc[4*i+1] = acc[4*i+1]*so + e*vv.y;
                acc[4*i+2] = acc[4*i+2]*so + e*vv.z;
                acc[4*i+3] = acc[4*i+3]*so + e*vv.w;
            }
            m = mn;
        }
        float inv = 1.0f / lsum;
        #pragma unroll
        for (int i = 0; i < 4; i++)
            *(float4*)(out + orow + (lane + i*32) * 4) =
                make_float4(acc[4*i+0]*inv, acc[4*i+1]*inv, acc[4*i+2]*inv, acc[4*i+3]*inv);
    } else {
        #pragma unroll
        for (int i = 0; i < 4; i++)
            *(float4*)(out + orow + (lane + i*32) * 4) = make_float4(0.f, 0.f, 0.f, 0.f);
    }

    if (blockIdx.x == 0 && blockIdx.y == 0 && threadIdx.x == 0) {
        double accd = 0.0, nb = 0.0;
        const double n = (double)L_;
        for (int bb = 0; bb < B_; bb++) {
            double kk = (double)g_nseg[bb];
            double lp = lgamma(n + 1.0) - lgamma(kk + 1.0) - lgamma(n - kk + 1.0)
                      + kk * log(0.2) + (n - kk) * log(0.8);
            accd += lp;
            nb   += kk;
        }
        double loss = -(accd / (double)B_) / n;
        out[POOLED_ELEMS + 0] = (float)loss;
        out[POOLED_ELEMS + 1] = (float)nb;
        out[POOLED_ELEMS + 2] = (float)(B_ * L_);
        g_isIw = 1;   // reset for next graph replay
    }
}

// ---------------- launch ----------------
extern "C" void kernel_launch(void* const* d_in, const int* in_sizes, int n_in,
                              void* d_out, int out_size) {
    const float* hidden = (const float*)d_in[0];
    const float* noise  = (const float*)d_in[1];
    const float* Wqb    = (const float*)d_in[2];
    const float* Wkb    = (const float*)d_in[3];
    const float* Wq     = (const float*)d_in[4];
    const float* Wk     = (const float*)d_in[5];
    const float* Wv     = (const float*)d_in[6];
    float* out = (float*)d_out;

    static int smem_set = 0;
    if (!smem_set) {
        cudaFuncSetAttribute(small_gemms,     cudaFuncAttributeMaxDynamicSharedMemorySize, GSMEM);
        cudaFuncSetAttribute(mma_gemm_merged, cudaFuncAttributeMaxDynamicSharedMemorySize, GSMEM);
        smem_set = 1;
    }

    prep_kernel<<<1792, 256>>>(Wqb, Wkb, Wq, Wk, Wv);
    rownorm_split_kernel<<<BL_, 128>>>(hidden);
    small_gemms<<<dim3(8,4), 256, GSMEM>>>();            // NT always; M (split out) flag-gated
    mma_gemm_merged<<<dim3(12,128), 256, GSMEM>>>();     // P = [V|Hn]; G flag-gated
    boundary_kernel<<<BL_/8, 256>>>(hidden, noise);
    scan_kernel<<<B_, 1024>>>();
    attn_warp_kernel<<<dim3(L_/8, B_), 256>>>(out);      // includes loss + flag reset
}

// round 17
// speedup vs baseline: 1.0289x; 1.0289x over previous
#include <cuda_runtime.h>
#include <cuda_fp16.h>
#include <math.h>
#include <stdint.h>

#define B_  8
#define L_  2048
#define D_  512
#define BL_ (B_*L_)          // 16384
#define POOLED_ELEMS ((size_t)BL_ * D_)   // 8388608
#define LDP 1024             // packed [V | Hn] row stride (halves)

// ---------------- scratch ----------------
__device__ float g_nrm[BL_];
__device__ float g_G[BL_ * D_];
__device__ __half g_Ph[(size_t)BL_ * LDP];   // fp16 packed [V | Hn]
__device__ __half g_Nhi[BL_ * D_];  // normh split — general (non-eye) path only
__device__ __half g_Nlo[BL_ * D_];
__device__ __half g_Ahi[BL_ * D_];  // hidden (fp16)
__device__ __half g_Whi[2 * D_ * D_];   // stacked [Wv ; NT]  (fp16)
__device__ __half g_WkThi[D_ * D_];
__device__ __half g_WkTlo[D_ * D_];
__device__ __half g_WqThi[D_ * D_];
__device__ __half g_WqTlo[D_ * D_];
__device__ __half g_QbThi[D_ * D_];
__device__ __half g_QbTlo[D_ * D_];
__device__ __half g_KbThi[D_ * D_];
__device__ __half g_KbTlo[D_ * D_];
__device__ __half g_Mhi[D_ * D_];
__device__ __half g_Mlo[D_ * D_];
__device__ int   g_hard[BL_];
__device__ int   g_segstart[BL_];
__device__ int   g_segcount[BL_];
__device__ int   g_nseg[B_];
__device__ int   g_isIw = 1;        // 1 if Wqb == Wkb == identity; reset at end of run

// ---------------- helpers ----------------
__device__ __forceinline__ uint32_t smem_u32(const void* p) {
    uint32_t a;
    asm("{ .reg .u64 t; cvta.to.shared.u64 t, %1; cvt.u32.u64 %0, t; }" : "=r"(a) : "l"(p));
    return a;
}
__device__ __forceinline__ float warpReduceSum(float v) {
    #pragma unroll
    for (int o = 16; o; o >>= 1) v += __shfl_xor_sync(0xffffffffu, v, o);
    return v;
}
__device__ __forceinline__ void split_f16(float x, __half& h, __half& l) {
    h = __float2half_rn(x);
    l = __float2half_rn(x - __half2float(h));
}
__device__ __forceinline__ float4 ld4h(const __half* p) {
    uint2 u = *(const uint2*)p;
    __half2 h0 = *(__half2*)&u.x;
    __half2 h1 = *(__half2*)&u.y;
    float2 f0 = __half22float2(h0);
    float2 f1 = __half22float2(h1);
    return make_float4(f0.x, f0.y, f1.x, f1.y);
}

#define LDM4(r, addr) \
    asm volatile("ldmatrix.sync.aligned.m8n8.x4.shared.b16 {%0,%1,%2,%3}, [%4];" \
        : "=r"((r)[0]), "=r"((r)[1]), "=r"((r)[2]), "=r"((r)[3]) : "r"(addr))

#define MMA_F16(d, a, b) \
    asm volatile("mma.sync.aligned.m16n8k16.row.col.f32.f16.f16.f32 " \
        "{%0,%1,%2,%3}, {%4,%5,%6,%7}, {%8,%9}, {%0,%1,%2,%3};" \
        : "+f"((d)[0]), "+f"((d)[1]), "+f"((d)[2]), "+f"((d)[3]) \
        : "r"((a)[0]), "r"((a)[1]), "r"((a)[2]), "r"((a)[3]), "r"((b)[0]), "r"((b)[1]))

#define CP16(dst, src) \
    asm volatile("cp.async.cg.shared.global [%0], [%1], 16;" :: "r"(dst), "l"(src))
#define CP_COMMIT() asm volatile("cp.async.commit_group;" ::: "memory")
#define CP_WAIT2()  asm volatile("cp.async.wait_group 2;" ::: "memory")
#define CP_WAIT1()  asm volatile("cp.async.wait_group 1;" ::: "memory")
#define CP_WAIT0()  asm volatile("cp.async.wait_group 0;" ::: "memory")

// ---------------- fused prep: identity check + Wv cvt + 4 transposes ----------------
__global__ __launch_bounds__(256) void prep_kernel(const float* __restrict__ wqb,
                                                   const float* __restrict__ wkb,
                                                   const float* __restrict__ wq,
                                                   const float* __restrict__ wk,
                                                   const float* __restrict__ wv) {
    int bx = blockIdx.x;
    if (bx < 512) {
        const float* src = (bx < 256) ? wqb : wkb;
        size_t i = (size_t)(bx & 255) * 256 + threadIdx.x;
        float4 v = ((const float4*)src)[i];
        size_t e0 = 4 * i;
        int row = (int)(e0 >> 9);
        int col = (int)(e0 & 511);
        bool ok = (v.x == ((col + 0 == row) ? 1.0f : 0.0f)) &
                  (v.y == ((col + 1 == row) ? 1.0f : 0.0f)) &
                  (v.z == ((col + 2 == row) ? 1.0f : 0.0f)) &
                  (v.w == ((col + 3 == row) ? 1.0f : 0.0f));
        if (!__syncthreads_and(ok)) {
            if (threadIdx.x == 0) atomicExch(&g_isIw, 0);
        }
    } else if (bx < 768) {
        size_t local = (size_t)(bx - 512) * 256 + threadIdx.x;
        float4 v = ((const float4*)wv)[local];
        __half hh[4];
        hh[0] = __float2half_rn(v.x); hh[1] = __float2half_rn(v.y);
        hh[2] = __float2half_rn(v.z); hh[3] = __float2half_rn(v.w);
        *(uint2*)(g_Whi + 4 * local) = *(uint2*)hh;
    } else {
        int t = bx - 768;
        int which = t >> 8;                 // 0:Wq 1:Wk 2:Wqb 3:Wkb
        int tb = t & 255;
        const float* in = (which == 0) ? wq : (which == 1) ? wk : (which == 2) ? wqb : wkb;
        __half* ohi = (which == 0) ? g_WqThi : (which == 1) ? g_WkThi : (which == 2) ? g_QbThi : g_KbThi;
        __half* olo = (which == 0) ? g_WqTlo : (which == 1) ? g_WkTlo : (which == 2) ? g_QbTlo : g_KbTlo;
        int bxx = tb & 15, byy = tb >> 4;
        int tx = threadIdx.x & 31, ty = threadIdx.x >> 5;
        __shared__ float tile[32][33];
        int x = bxx * 32 + tx;
        int y = byy * 32 + ty;
        #pragma unroll
        for (int i = 0; i < 32; i += 8)
            tile[ty + i][tx] = in[(size_t)(y + i) * 512 + x];
        __syncthreads();
        x = byy * 32 + tx;
        y = bxx * 32 + ty;
        #pragma unroll
        for (int i = 0; i < 32; i += 8) {
            float v = tile[tx][ty + i];
            __half h, l;
            split_f16(v, h, l);
            ohi[(size_t)(y + i) * 512 + x] = h;
            olo[(size_t)(y + i) * 512 + x] = l;
        }
    }
}

// ---------------- fused norm + boundary (8 tokens/block, 1-row halo) ----------------
// Bit-identical to the old rownorm block-reduce + boundary warp dot: per-group
// warp reduces summed in sm[0..3] order, then verbatim per-element divisions.
__global__ __launch_bounds__(256) void norm_boundary_kernel(const float* __restrict__ h,
                                                            const float* __restrict__ noise_u) {
    __shared__ float srow[9][512];
    __shared__ float snrm[9];
    int warp = threadIdx.x >> 5, lane = threadIdx.x & 31;
    int gw0 = blockIdx.x * 8;
    int isI = g_isIw;

    for (int r = warp; r < 9; r += 8) {
        int grow = gw0 - 1 + r;
        if (grow >= 0) {
            const float4* src = (const float4*)(h + (size_t)grow * D_);
            float4 vv[4];
            float p[4];
            #pragma unroll
            for (int i = 0; i < 4; i++) {
                float4 v = src[lane + i*32];
                vv[i] = v;
                *(float4*)&srow[r][(lane + i*32) * 4] = v;
                p[i] = v.x*v.x + v.y*v.y + v.z*v.z + v.w*v.w;
            }
            // replicate old 128-thread tree: sm[i] = warp-reduce of group i, tot = sm0+sm1+sm2+sm3
            float s0 = warpReduceSum(p[0]);
            float s1 = warpReduceSum(p[1]);
            float s2 = warpReduceSum(p[2]);
            float s3 = warpReduceSum(p[3]);
            float tot = s0 + s1 + s2 + s3;
            float nrm = fmaxf(sqrtf(tot), 1e-12f);
            if (lane == 0) snrm[r] = nrm;
            if (r >= 1) {
                if (lane == 0) g_nrm[grow] = nrm;
                size_t base = (size_t)grow * D_;
                #pragma unroll
                for (int i = 0; i < 4; i++) {
                    __half hh[4];
                    hh[0] = __float2half_rn(vv[i].x); hh[1] = __float2half_rn(vv[i].y);
                    hh[2] = __float2half_rn(vv[i].z); hh[3] = __float2half_rn(vv[i].w);
                    *(uint2*)(g_Ahi + base + (lane + i*32) * 4) = *(uint2*)hh;
                }
                if (!isI) {
                    #pragma unroll
                    for (int i = 0; i < 4; i++) {
                        __half hh[4], ll[4];
                        split_f16(vv[i].x / nrm, hh[0], ll[0]);
                        split_f16(vv[i].y / nrm, hh[1], ll[1]);
                        split_f16(vv[i].z / nrm, hh[2], ll[2]);
                        split_f16(vv[i].w / nrm, hh[3], ll[3]);
                        *(uint2*)(g_Nhi + base + (lane + i*32) * 4) = *(uint2*)hh;
                        *(uint2*)(g_Nlo + base + (lane + i*32) * 4) = *(uint2*)ll;
                    }
                }
            }
        } else {
            if (lane == 0) snrm[r] = 1.0f;
        }
    }
    __syncthreads();

    if (!isI) return;   // general path: boundary computed after the G GEMM

    int gw = gw0 + warp;
    int t = gw & (L_ - 1);
    float prob;
    if (t == 0) {
        prob = 1.0f;
    } else {
        float n1 = snrm[warp];
        float n2 = snrm[warp + 1];
        float s = 0.0f;
        #pragma unroll
        for (int i = 0; i < 4; i++) {
            float4 aa = *(float4*)&srow[warp][(lane + i*32) * 4];
            float4 cc = *(float4*)&srow[warp + 1][(lane + i*32) * 4];
            float ax = aa.x / n1, ay = aa.y / n1, az = aa.z / n1, aw = aa.w / n1;
            float cx = cc.x / n2, cy = cc.y / n2, cz = cc.z / n2, cw = cc.w / n2;
            s += ax*cx + ay*cy + az*cz + aw*cw;
        }
        s = warpReduceSum(s);
        prob = fminf(fmaxf((1.0f - s) * 0.5f, 0.0f), 1.0f);
    }
    if (lane == 0) {
        float pc = fminf(fmaxf(prob, 1e-6f), 1.0f - 1e-6f);
        float logits = logf(pc) - log1pf(-pc);
        float u = noise_u[gw];
        float noise = logf(u) - log1pf(-u);
        float z = logits + noise;
        float soft = 1.0f / (1.0f + expf(-z));
        g_hard[gw] = (soft > 0.5f) ? 1 : 0;
    }
}

// ---------------- pipelined split-fp16 HMMA GEMM body ----------------
// OMODE: 0 = fp32 out, 1 = fp16 out, 2 = fp16 hi/lo split out (Cv, Cv2)
#define APITCH 40
#define GARR   (128 * APITCH * 2)   // 10240 B per array
#define GSTAGE (4 * GARR)           // 40960 B per 3-pass stage
#define GSMEM  (2 * GSTAGE)         // 81920 B

template<int NPASS, int OMODE>
__device__ __forceinline__ void gemm_body(
    const __half* __restrict__ Ahi, const __half* __restrict__ Alo,
    const __half* __restrict__ Bhi, const __half* __restrict__ Blo,
    void* __restrict__ Cv, void* __restrict__ Cv2, int ldc, int m0, int n0, char* smem)
{
    int tid = threadIdx.x;
    int lane = tid & 31, wid = tid >> 5;
    int warp_m = wid >> 1;
    int warp_n = wid & 1;

    float acc[2][8][4];
    #pragma unroll
    for (int mt = 0; mt < 2; mt++)
        #pragma unroll
        for (int nt = 0; nt < 8; nt++)
            #pragma unroll
            for (int r = 0; r < 4; r++) acc[mt][nt][r] = 0.f;

    uint32_t sbase = smem_u32(smem);
    int lrow  = tid >> 1;
    int lslot = (tid & 1) * 2;

    int a_r  = lane & 15;
    int a_c8 = (lane >> 4) * 8;
    int b_r  = (lane & 7) + ((lane >> 4) * 8);
    int b_c8 = ((lane >> 3) & 1) * 8;

    auto compute = [&](uint32_t aB, uint32_t alB, uint32_t bB, uint32_t blB) {
        #pragma unroll
        for (int ks = 0; ks < 2; ks++) {
            int kofs = ks * 16;
            uint32_t ahi[2][4], alo[2][4];
            #pragma unroll
            for (int mt = 0; mt < 2; mt++) {
                int r = warp_m * 32 + mt * 16 + a_r;
                uint32_t ab = (uint32_t)(r * APITCH + kofs + a_c8) * 2;
                LDM4(ahi[mt], aB + ab);
                if (NPASS >= 2) LDM4(alo[mt], alB + ab);
            }
            #pragma unroll
            for (int nt2 = 0; nt2 < 4; nt2++) {
                int r = warp_n * 64 + nt2 * 16 + b_r;
                uint32_t bb = (uint32_t)(r * APITCH + kofs + b_c8) * 2;
                uint32_t bhi[4], blo[4];
                LDM4(bhi, bB + bb);
                if (NPASS == 3) LDM4(blo, blB + bb);
                #pragma unroll
                for (int half = 0; half < 2; half++) {
                    int nt = nt2 * 2 + half;
                    uint32_t* bh = bhi + half * 2;
                    uint32_t* bl = blo + half * 2;
                    #pragma unroll
                    for (int mt = 0; mt < 2; mt++) {
                        MMA_F16(acc[mt][nt], ahi[mt], bh);
                        if (NPASS >= 2) MMA_F16(acc[mt][nt], alo[mt], bh);
                        if (NPASS == 3) MMA_F16(acc[mt][nt], ahi[mt], bl);
                    }
                }
            }
        }
    };

    if (NPASS == 1) {
        const uint32_t STG = 2 * GARR;
        auto load1 = [&](int kc, uint32_t st) {
            int gk = kc * 32;
            #pragma unroll
            for (int s = 0; s < 2; s++) {
                int slot = lslot + s;
                size_t goff = (size_t)(m0 + lrow) * 512 + gk + slot * 8;
                size_t boff = (size_t)(n0 + lrow) * 512 + gk + slot * 8;
                uint32_t soff = (uint32_t)(lrow * APITCH + slot * 8) * 2;
                CP16(st + soff,        Ahi + goff);
                CP16(st + GARR + soff, Bhi + boff);
            }
            CP_COMMIT();
        };
        load1(0, sbase + 0 * STG);
        load1(1, sbase + 1 * STG);
        for (int kc = 0; kc < 16; kc++) {
            if (kc + 2 < 16) {
                load1(kc + 2, sbase + (uint32_t)((kc + 2) & 3) * STG);
                CP_WAIT2();
            } else {
                CP_WAIT0();
            }
            __syncthreads();
            uint32_t cur = sbase + (uint32_t)(kc & 3) * STG;
            compute(cur, cur, cur + GARR, cur + GARR);
        }
    } else {
        auto load3 = [&](int kc, uint32_t st) {
            int gk = kc * 32;
            #pragma unroll
            for (int s = 0; s < 2; s++) {
                int slot = lslot + s;
                size_t goff = (size_t)(m0 + lrow) * 512 + gk + slot * 8;
                size_t boff = (size_t)(n0 + lrow) * 512 + gk + slot * 8;
                uint32_t soff = (uint32_t)(lrow * APITCH + slot * 8) * 2;
                CP16(st + 0*GARR + soff, Ahi + goff);
                CP16(st + 1*GARR + soff, Alo + goff);
                CP16(st + 2*GARR + soff, Bhi + boff);
                CP16(st + 3*GARR + soff, Blo + boff);
            }
            CP_COMMIT();
        };
        load3(0, sbase);
        for (int kc = 0; kc < 16; kc++) {
            uint32_t cur = sbase + (uint32_t)(kc & 1) * GSTAGE;
            if (kc + 1 < 16) {
                load3(kc + 1, sbase + (uint32_t)((kc + 1) & 1) * GSTAGE);
                CP_WAIT1();
            } else {
                CP_WAIT0();
            }
            __syncthreads();
            compute(cur + 0*GARR, cur + 1*GARR, cur + 2*GARR, cur + 3*GARR);
            __syncthreads();
        }
    }

    #pragma unroll
    for (int mt = 0; mt < 2; mt++) {
        int r0 = m0 + warp_m * 32 + mt * 16 + (lane >> 2);
        #pragma unroll
        for (int nt = 0; nt < 8; nt++) {
            int c = n0 + warp_n * 64 + nt * 8 + (lane & 3) * 2;
            if (OMODE == 1) {
                __half* C = (__half*)Cv;
                *(__half2*)(C + (size_t)r0 * ldc + c) =
                    __floats2half2_rn(acc[mt][nt][0], acc[mt][nt][1]);
                *(__half2*)(C + (size_t)(r0 + 8) * ldc + c) =
                    __floats2half2_rn(acc[mt][nt][2], acc[mt][nt][3]);
            } else if (OMODE == 2) {
                __half* Ch = (__half*)Cv;
                __half* Cl = (__half*)Cv2;
                __half h0, l0, h1, l1;
                split_f16(acc[mt][nt][0], h0, l0); split_f16(acc[mt][nt][1], h1, l1);
                *(__half2*)(Ch + (size_t)r0 * ldc + c) = __half2(h0, h1);
                *(__half2*)(Cl + (size_t)r0 * ldc + c) = __half2(l0, l1);
                split_f16(acc[mt][nt][2], h0, l0); split_f16(acc[mt][nt][3], h1, l1);
                *(__half2*)(Ch + (size_t)(r0 + 8) * ldc + c) = __half2(h0, h1);
                *(__half2*)(Cl + (size_t)(r0 + 8) * ldc + c) = __half2(l0, l1);
            } else {
                float* C = (float*)Cv;
                *(float2*)(C + (size_t)r0 * ldc + c)       = make_float2(acc[mt][nt][0], acc[mt][nt][1]);
                *(float2*)(C + (size_t)(r0 + 8) * ldc + c) = make_float2(acc[mt][nt][2], acc[mt][nt][3]);
            }
        }
    }
}

// fused small GEMMs: bx<4 -> NT = Wk^T Wq (fp16 out); bx>=4 -> M split-fp16 out (gated)
__global__ __launch_bounds__(256, 2) void small_gemms() {
    extern __shared__ char smem[];
    int bx = blockIdx.x;
    int m0 = blockIdx.y * 128;
    if (bx < 4) {
        gemm_body<3, 1>(g_WkThi, g_WkTlo, g_WqThi, g_WqTlo,
                        g_Whi + (size_t)D_ * D_, nullptr, 512, m0, bx * 128, smem);
    } else {
        if (g_isIw) return;
        gemm_body<3, 2>(g_QbThi, g_QbTlo, g_KbThi, g_KbTlo,
                        g_Mhi, g_Mlo, 512, m0, (bx - 4) * 128, smem);
    }
}

// merged big GEMM: bx<8 -> P tile (1-pass, fp16 out, [V|Hn]); bx>=8 -> G tile (gated)
__global__ __launch_bounds__(256, 2) void mma_gemm_merged() {
    extern __shared__ char smem[];
    int bx = blockIdx.x;
    int m0 = blockIdx.y * 128;
    if (bx < 8) {
        gemm_body<1, 1>(g_Ahi, g_Ahi, g_Whi, g_Whi, g_Ph, nullptr, LDP, m0, bx * 128, smem);
    } else {
        if (g_isIw) return;
        gemm_body<3, 0>(g_Nhi, g_Nlo, g_Mhi, g_Mlo, g_G, nullptr, 512, m0, (bx - 8) * 128, smem);
    }
}

// ---------------- boundary decisions, general (non-eye) path only ----------------
__global__ __launch_bounds__(256) void boundary_general_kernel(const float* __restrict__ hidden,
                                                               const float* __restrict__ noise_u) {
    if (g_isIw) return;
    int gw = blockIdx.x * 8 + (threadIdx.x >> 5);
    if (gw >= BL_) return;
    int t = gw & (L_ - 1);
    int lane = threadIdx.x & 31;
    float prob;
    if (t == 0) {
        prob = 1.0f;
    } else {
        float n1 = g_nrm[gw - 1];
        const float4* x = (const float4*)(hidden + (size_t)(gw - 1) * D_);
        const float4* y = (const float4*)(g_G + (size_t)gw * D_);
        float s = 0.0f;
        #pragma unroll
        for (int i = 0; i < 4; i++) {
            float4 aa = x[lane + i*32];
            float4 cc = y[lane + i*32];
            float ax = aa.x / n1, ay = aa.y / n1, az = aa.z / n1, aw = aa.w / n1;
            s += ax*cc.x + ay*cc.y + az*cc.z + aw*cc.w;
        }
        s = warpReduceSum(s);
        prob = fminf(fmaxf((1.0f - s) * 0.5f, 0.0f), 1.0f);
    }
    if ((threadIdx.x & 31) == 0) {
        float pc = fminf(fmaxf(prob, 1e-6f), 1.0f - 1e-6f);
        float logits = logf(pc) - log1pf(-pc);
        float u = noise_u[gw];
        float noise = logf(u) - log1pf(-u);
        float z = logits + noise;
        float soft = 1.0f / (1.0f + expf(-z));
        g_hard[gw] = (soft > 0.5f) ? 1 : 0;
    }
}

// ---------------- per-batch segmentation (warp-shuffle scan) ----------------
__global__ __launch_bounds__(1024) void scan_kernel() {
    int b = blockIdx.x;
    __shared__ int wsum[32];
    __shared__ int st[L_];
    __shared__ int ns_sh;
    int tid = threadIdx.x, lane = tid & 31, warp = tid >> 5;
    int h0 = g_hard[b*L_ + 2*tid];
    int h1 = g_hard[b*L_ + 2*tid + 1];
    int v = h0 + h1;
    int x = v;
    #pragma unroll
    for (int o = 1; o < 32; o <<= 1) {
        int y = __shfl_up_sync(0xffffffffu, x, o);
        if (lane >= o) x += y;
    }
    if (lane == 31) wsum[warp] = x;
    __syncthreads();
    if (warp == 0) {
        int tsum = wsum[lane];
        #pragma unroll
        for (int o = 1; o < 32; o <<= 1) {
            int y = __shfl_up_sync(0xffffffffu, tsum, o);
            if (lane >= o) tsum += y;
        }
        wsum[lane] = tsum;
        if (lane == 31) { ns_sh = tsum; g_nseg[b] = tsum; }
    }
    __syncthreads();
    int incl = x + (warp ? wsum[warp - 1] : 0);
    int excl = incl - v;
    int i0 = excl + h0;
    int i1 = excl + h0 + h1;
    if (h0) st[i0 - 1] = 2*tid;
    if (h1) st[i1 - 1] = 2*tid + 1;
    __syncthreads();
    int ns = ns_sh;
    for (int s = tid; s < ns; s += 1024) {
        int sbgn = st[s];
        int send = (s + 1 < ns) ? st[s + 1] : L_;
        g_segstart[b*L_ + s] = sbgn;
        g_segcount[b*L_ + s] = send - sbgn;
    }
}

// ---------------- warp-per-segment attention + fused loss/scalars ----------------
__global__ __launch_bounds__(256) void attn_warp_kernel(float* __restrict__ out) {
    int b = blockIdx.y;
    int w = threadIdx.x >> 5, lane = threadIdx.x & 31;
    int s = blockIdx.x * 8 + w;
    size_t orow = (size_t)(b*L_ + s) * D_;

    if (s < g_nseg[b]) {
        int start = g_segstart[b*L_ + s];
        int cnt   = g_segcount[b*L_ + s];

        float q[16];
        #pragma unroll
        for (int i = 0; i < 16; i++) q[i] = 0.f;
        for (int l = 0; l < cnt; l++) {
            const __half* hn = g_Ph + (size_t)(b*L_ + start + l) * LDP + 512;
            #pragma unroll
            for (int i = 0; i < 4; i++) {
                float4 v = ld4h(hn + (lane + i*32) * 4);
                q[4*i+0] += v.x; q[4*i+1] += v.y; q[4*i+2] += v.z; q[4*i+3] += v.w;
            }
        }
        float invc = 1.0f / (float)cnt;
        #pragma unroll
        for (int i = 0; i < 16; i++) q[i] *= invc;

        const float scale = 0.04419417382415922f;   // 512^-0.5
        float m = -INFINITY, lsum = 0.f;
        float acc[16];
        #pragma unroll
        for (int i = 0; i < 16; i++) acc[i] = 0.f;

        for (int l = 0; l < cnt; l++) {
            const __half* hr = g_Ahi + (size_t)(b*L_ + start + l) * D_;
            float dp = 0.f;
            #pragma unroll
            for (int i = 0; i < 4; i++) {
                float4 kk = ld4h(hr + (lane + i*32) * 4);
                dp += q[4*i+0]*kk.x + q[4*i+1]*kk.y + q[4*i+2]*kk.z + q[4*i+3]*kk.w;
            }
            dp = warpReduceSum(dp) * scale;
            float mn = fmaxf(m, dp);
            float so = expf(m - mn);
            float e  = expf(dp - mn);
            lsum = lsum * so + e;
            const __half* vr = g_Ph + (size_t)(b*L_ + start + l) * LDP;
            #pragma unroll
            for (int i = 0; i < 4; i++) {
                float4 vv = ld4h(vr + (lane + i*32) * 4);
                acc[4*i+0] = acc[4*i+0]*so + e*vv.x;
                acc[4*i+1] = acc[4*i+1]*so + e*vv.y;
                acc[4*i+2] = acc[4*i+2]*so + e*vv.z;
                acc[4*i+3] = acc[4*i+3]*so + e*vv.w;
            }
            m = mn;
        }
        float inv = 1.0f / lsum;
        #pragma unroll
        for (int i = 0; i < 4; i++)
            *(float4*)(out + orow + (lane + i*32) * 4) =
                make_float4(acc[4*i+0]*inv, acc[4*i+1]*inv, acc[4*i+2]*inv, acc[4*i+3]*inv);
    } else {
        #pragma unroll
        for (int i = 0; i < 4; i++)
            *(float4*)(out + orow + (lane + i*32) * 4) = make_float4(0.f, 0.f, 0.f, 0.f);
    }

    if (blockIdx.x == 0 && blockIdx.y == 0 && threadIdx.x == 0) {
        double accd = 0.0, nb = 0.0;
        const double n = (double)L_;
        for (int bb = 0; bb < B_; bb++) {
            double kk = (double)g_nseg[bb];
            double lp = lgamma(n + 1.0) - lgamma(kk + 1.0) - lgamma(n - kk + 1.0)
                      + kk * log(0.2) + (n - kk) * log(0.8);
            accd += lp;
            nb   += kk;
        }
        double loss = -(accd / (double)B_) / n;
        out[POOLED_ELEMS + 0] = (float)loss;
        out[POOLED_ELEMS + 1] = (float)nb;
        out[POOLED_ELEMS + 2] = (float)(B_ * L_);
        g_isIw = 1;   // reset for next graph replay
    }
}

// ---------------- launch ----------------
extern "C" void kernel_launch(void* const* d_in, const int* in_sizes, int n_in,
                              void* d_out, int out_size) {
    const float* hidden = (const float*)d_in[0];
    const float* noise  = (const float*)d_in[1];
    const float* Wqb    = (const float*)d_in[2];
    const float* Wkb    = (const float*)d_in[3];
    const float* Wq     = (const float*)d_in[4];
    const float* Wk     = (const float*)d_in[5];
    const float* Wv     = (const float*)d_in[6];
    float* out = (float*)d_out;

    static int smem_set = 0;
    if (!smem_set) {
        cudaFuncSetAttribute(small_gemms,     cudaFuncAttributeMaxDynamicSharedMemorySize, GSMEM);
        cudaFuncSetAttribute(mma_gemm_merged, cudaFuncAttributeMaxDynamicSharedMemorySize, GSMEM);
        smem_set = 1;
    }

    prep_kernel<<<1792, 256>>>(Wqb, Wkb, Wq, Wk, Wv);
    norm_boundary_kernel<<<BL_/8, 256>>>(hidden, noise);   // norms + Ahi (+ hard when isIw)
    small_gemms<<<dim3(8,4), 256, GSMEM>>>();              // NT always; M flag-gated
    mma_gemm_merged<<<dim3(12,128), 256, GSMEM>>>();       // P = [V|Hn]; G flag-gated
    boundary_general_kernel<<<BL_/8, 256>>>(hidden, noise);// no-op when isIw
    scan_kernel<<<B_, 1024>>>();
    attn_warp_kernel<<<dim3(L_/8, B_), 256>>>(out);        // includes loss + flag reset
}